// round 1
// baseline (speedup 1.0000x reference)
#include <cuda_runtime.h>
#include <math.h>

// Problem constants
#define BB 8
#define LL 1024
#define DD 1280
#define HH 16
#define HD 80
#define MTOT (BB*LL)      // 8192
#define NQKV (3*DD)       // 3840

// Scratch (allocation-free rule: __device__ globals)
__device__ float g_q[(size_t)BB*HH*LL*HD];   // [B,H,L,hd]
__device__ float g_k[(size_t)BB*HH*LL*HD];
__device__ float g_v[(size_t)BB*HH*LL*HD];
__device__ float g_o[(size_t)BB*LL*DD];      // attention output, [B,L,D]

// ---------------------------------------------------------------------------
// SGEMM: C[M,N] = A[M,K] @ W[K,N] + bias[N]
// 128x128 block tile, BK=8, 256 threads, 8x8 per-thread microtile.
// MODE 0: plain row-major C
// MODE 1: QKV scatter epilogue into g_q/g_k/g_v ([B,H,L,hd])
// MODE 2: like MODE 0 but A is ignored and g_o is used as the A operand
// ---------------------------------------------------------------------------
template<int MODE>
__global__ __launch_bounds__(256) void sgemm_kernel(
    const float* __restrict__ A, const float* __restrict__ W,
    const float* __restrict__ bias, float* __restrict__ C,
    int M, int N, int K)
{
    __shared__ float As[8][128];
    __shared__ float Bs[8][128];

    const float* Aeff = (MODE == 2) ? (const float*)g_o : A;

    const int tid = threadIdx.x;
    const int m0 = blockIdx.y * 128;
    const int n0 = blockIdx.x * 128;

    // A loader: one float4 per thread, 128 rows x 8 cols
    const int am = tid >> 1;           // 0..127
    const int ak = (tid & 1) * 4;      // 0 or 4
    // B loader: one float4 per thread, 8 rows x 128 cols
    const int bk = tid >> 5;           // 0..7
    const int bn = (tid & 31) * 4;     // 0..124

    const int ty = tid >> 4;           // 0..15 (row group)
    const int tx = tid & 15;           // 0..15 (col group)

    float acc[8][8];
#pragma unroll
    for (int i = 0; i < 8; i++)
#pragma unroll
        for (int j = 0; j < 8; j++) acc[i][j] = 0.f;

    const float* Aptr = Aeff + (size_t)(m0 + am) * K + ak;
    const float* Wptr = W + (size_t)bk * N + n0 + bn;

    for (int k0 = 0; k0 < K; k0 += 8) {
        float4 av = *(const float4*)(Aptr + k0);
        float4 bv = *(const float4*)(Wptr + (size_t)k0 * N);
        __syncthreads();
        As[ak + 0][am] = av.x;
        As[ak + 1][am] = av.y;
        As[ak + 2][am] = av.z;
        As[ak + 3][am] = av.w;
        *(float4*)&Bs[bk][bn] = bv;
        __syncthreads();
#pragma unroll
        for (int k = 0; k < 8; k++) {
            float4 a0 = *(const float4*)&As[k][ty * 8];
            float4 a1 = *(const float4*)&As[k][ty * 8 + 4];
            float4 b0 = *(const float4*)&Bs[k][tx * 8];
            float4 b1 = *(const float4*)&Bs[k][tx * 8 + 4];
            float ar[8] = {a0.x, a0.y, a0.z, a0.w, a1.x, a1.y, a1.z, a1.w};
            float br[8] = {b0.x, b0.y, b0.z, b0.w, b1.x, b1.y, b1.z, b1.w};
#pragma unroll
            for (int i = 0; i < 8; i++)
#pragma unroll
                for (int j = 0; j < 8; j++)
                    acc[i][j] = fmaf(ar[i], br[j], acc[i][j]);
        }
    }

    if (MODE == 0 || MODE == 2) {
#pragma unroll
        for (int i = 0; i < 8; i++) {
            int r = m0 + ty * 8 + i;
            float* crow = C + (size_t)r * N + n0 + tx * 8;
            const float* brow = bias + n0 + tx * 8;
            float4 o0, o1;
            o0.x = acc[i][0] + brow[0]; o0.y = acc[i][1] + brow[1];
            o0.z = acc[i][2] + brow[2]; o0.w = acc[i][3] + brow[3];
            o1.x = acc[i][4] + brow[4]; o1.y = acc[i][5] + brow[5];
            o1.z = acc[i][6] + brow[6]; o1.w = acc[i][7] + brow[7];
            *(float4*)(crow)     = o0;
            *(float4*)(crow + 4) = o1;
        }
    } else {
        // QKV scatter
#pragma unroll
        for (int i = 0; i < 8; i++) {
            int r = m0 + ty * 8 + i;
            int bidx = r >> 10;     // /1024
            int l = r & 1023;
#pragma unroll
            for (int j = 0; j < 8; j++) {
                int c = n0 + tx * 8 + j;
                float val = acc[i][j] + bias[c];
                int which = c / DD;
                int rem = c - which * DD;
                int h = rem / HD;
                int dd = rem - h * HD;
                float* dst = (which == 0) ? g_q : (which == 1) ? g_k : g_v;
                dst[((size_t)((bidx * HH + h) * LL + l)) * HD + dd] = val;
            }
        }
    }
}

// ---------------------------------------------------------------------------
// RoPE on g_q, g_k in place. emb = concat(rot, rot); half = 40.
// out[j]    = x[j]*cos(r[j])    - x[j+40]*sin(r[j])
// out[j+40] = x[j+40]*cos(r[j]) + x[j]*sin(r[j])
// ---------------------------------------------------------------------------
__global__ void rope_kernel(const float* __restrict__ rot)
{
    const int total = BB * HH * LL * (HD / 2);   // 5,242,880
    int idx = blockIdx.x * blockDim.x + threadIdx.x;
    if (idx >= total) return;
    int j = idx % 40;
    int l = (idx / 40) & 1023;
    int bh = idx / (40 * 1024);
    float r = rot[l * 40 + j];
    float s, c;
    sincosf(r, &s, &c);
    size_t base = ((size_t)bh * LL + l) * HD;

    float q1 = g_q[base + j], q2 = g_q[base + j + 40];
    g_q[base + j]      = q1 * c - q2 * s;
    g_q[base + j + 40] = q2 * c + q1 * s;

    float k1 = g_k[base + j], k2 = g_k[base + j + 40];
    g_k[base + j]      = k1 * c - k2 * s;
    g_k[base + j + 40] = k2 * c + k1 * s;
}

// ---------------------------------------------------------------------------
// Causal flash attention, fp32. One thread per query row (128 rows/block).
// K/V tiled 32 rows in shared; online softmax with per-16-key rescale.
// Output written into g_o in [B,L,D] layout (ready for proj GEMM).
// ---------------------------------------------------------------------------
__global__ __launch_bounds__(128) void attn_kernel()
{
    __shared__ float Ks[32][80];
    __shared__ float Vs[32][80];

    const int bh = blockIdx.y;                 // 0..127
    const int row = blockIdx.x * 128 + threadIdx.x;
    const float scale = 0.1118033988749895f;   // 1/sqrt(80)

    const float* qp = g_q + ((size_t)bh * LL + row) * HD;
    float q[80];
#pragma unroll
    for (int d4 = 0; d4 < 20; d4++) {
        float4 t = ((const float4*)qp)[d4];
        q[4*d4+0] = t.x * scale; q[4*d4+1] = t.y * scale;
        q[4*d4+2] = t.z * scale; q[4*d4+3] = t.w * scale;
    }

    float acc[80];
#pragma unroll
    for (int d = 0; d < 80; d++) acc[d] = 0.f;
    float mrun = -3.0e38f, lsum = 0.f;

    const int ntiles = (blockIdx.x + 1) * 4;   // 32-key tiles up to causal edge
    const float4* kbase = (const float4*)(g_k + (size_t)bh * LL * HD);
    const float4* vbase = (const float4*)(g_v + (size_t)bh * LL * HD);

    for (int t = 0; t < ntiles; t++) {
        __syncthreads();
#pragma unroll
        for (int i = 0; i < 5; i++) {
            int idx = threadIdx.x + i * 128;   // 0..639 float4s
            ((float4*)Ks)[idx] = kbase[t * 640 + idx];
            ((float4*)Vs)[idx] = vbase[t * 640 + idx];
        }
        __syncthreads();
        int kg0 = t * 32;
#pragma unroll 1
        for (int g = 0; g < 2; g++) {
            float s[16];
#pragma unroll
            for (int j = 0; j < 16; j++) {
                int jj = g * 16 + j;
                const float4* krow = (const float4*)Ks[jj];
                float sum = 0.f;
#pragma unroll
                for (int d4 = 0; d4 < 20; d4++) {
                    float4 kv = krow[d4];
                    sum = fmaf(q[4*d4+0], kv.x, sum);
                    sum = fmaf(q[4*d4+1], kv.y, sum);
                    sum = fmaf(q[4*d4+2], kv.z, sum);
                    sum = fmaf(q[4*d4+3], kv.w, sum);
                }
                s[j] = (kg0 + jj <= row) ? sum : -3.0e38f;
            }
            float mn = mrun;
#pragma unroll
            for (int j = 0; j < 16; j++) mn = fmaxf(mn, s[j]);
            float corr = __expf(mrun - mn);
            mrun = mn;
            lsum *= corr;
#pragma unroll
            for (int d = 0; d < 80; d++) acc[d] *= corr;
#pragma unroll
            for (int j = 0; j < 16; j++) {
                float p = __expf(s[j] - mn);
                lsum += p;
                const float4* vrow = (const float4*)Vs[g * 16 + j];
#pragma unroll
                for (int d4 = 0; d4 < 20; d4++) {
                    float4 vv = vrow[d4];
                    acc[4*d4+0] = fmaf(p, vv.x, acc[4*d4+0]);
                    acc[4*d4+1] = fmaf(p, vv.y, acc[4*d4+1]);
                    acc[4*d4+2] = fmaf(p, vv.z, acc[4*d4+2]);
                    acc[4*d4+3] = fmaf(p, vv.w, acc[4*d4+3]);
                }
            }
        }
    }

    float inv = 1.f / lsum;
    const int b = bh >> 4, h = bh & 15;
    float* op = g_o + ((size_t)(b * LL + row)) * DD + h * HD;
#pragma unroll
    for (int d4 = 0; d4 < 20; d4++) {
        float4 o;
        o.x = acc[4*d4+0] * inv; o.y = acc[4*d4+1] * inv;
        o.z = acc[4*d4+2] * inv; o.w = acc[4*d4+3] * inv;
        *(float4*)(op + 4 * d4) = o;
    }
}

// ---------------------------------------------------------------------------
extern "C" void kernel_launch(void* const* d_in, const int* in_sizes, int n_in,
                              void* d_out, int out_size)
{
    const float* hidden = (const float*)d_in[0];   // (8,1024,1280)
    const float* rot    = (const float*)d_in[1];   // (1024,40)
    const float* Wqkv   = (const float*)d_in[2];   // (1280,3840)
    const float* bqkv   = (const float*)d_in[3];   // (3840,)
    const float* Wproj  = (const float*)d_in[4];   // (1280,1280)
    const float* bproj  = (const float*)d_in[5];   // (1280,)
    float* out = (float*)d_out;                    // (8,1024,1280)

    // 1) QKV GEMM with scatter + bias
    {
        dim3 grid(NQKV / 128, MTOT / 128);         // (30, 64)
        sgemm_kernel<1><<<grid, 256>>>(hidden, Wqkv, bqkv, nullptr,
                                       MTOT, NQKV, DD);
    }

    // 2) RoPE on q, k
    {
        const int total = BB * HH * LL * (HD / 2);
        rope_kernel<<<(total + 255) / 256, 256>>>(rot);
    }

    // 3) Causal attention
    {
        dim3 grid(LL / 128, BB * HH);              // (8, 128)
        attn_kernel<<<grid, 128>>>();
    }

    // 4) Output projection (reads g_o internally)
    {
        dim3 grid(DD / 128, MTOT / 128);           // (10, 64)
        sgemm_kernel<2><<<grid, 256>>>(nullptr, Wproj, bproj, out,
                                       MTOT, DD, DD);
    }
}

// round 8
// speedup vs baseline: 1.8039x; 1.8039x over previous
#include <cuda_runtime.h>
#include <cuda_bf16.h>
#include <cstdint>
#include <stdint.h>
#include <math.h>

// Problem constants
#define BB 8
#define LL 1024
#define DD 1280
#define HH 16
#define HD 80
#define MTOT (BB*LL)      // 8192
#define KP   3840         // stacked K' = 3*1280

// Scratch (__device__ globals; allocation-free rule)
__device__ float g_q[(size_t)BB*HH*LL*HD];   // [B,H,L,hd]
__device__ float g_k[(size_t)BB*HH*LL*HD];
__device__ float g_v[(size_t)BB*HH*LL*HD];
__device__ float g_o[(size_t)BB*LL*DD];      // attention output, [B,L,D]
__device__ __nv_bfloat16 g_a1[(size_t)MTOT*KP];   // [8192][3840] hi|lo|hi of hidden
__device__ __nv_bfloat16 g_a2[(size_t)MTOT*KP];   // [8192][3840] hi|lo|hi of attn out
__device__ __nv_bfloat16 g_w1t[(size_t)3840*KP];  // Wqkv^T stacked: [n][k']
__device__ __nv_bfloat16 g_w2t[(size_t)1280*KP];  // Wproj^T stacked: [n][k']

// ---------------------------------------------------------------------------
// PTX helpers (compute_103-safe: cp.async + ldmatrix + mma.sync only)
// ---------------------------------------------------------------------------
__device__ __forceinline__ unsigned smem_u32(const void* p) {
    unsigned a;
    asm("{ .reg .u64 t; cvta.to.shared.u64 t, %1; cvt.u32.u64 %0, t; }" : "=r"(a) : "l"(p));
    return a;
}
#define CP_ASYNC16(dst, src) \
    asm volatile("cp.async.cg.shared.global [%0], [%1], 16;" :: "r"(dst), "l"(src) : "memory")
#define CP_COMMIT() asm volatile("cp.async.commit_group;" ::: "memory")
#define CP_WAIT1()  asm volatile("cp.async.wait_group 1;" ::: "memory")
#define CP_WAIT0()  asm volatile("cp.async.wait_group 0;" ::: "memory")

__device__ __forceinline__ void ldsm_x4(unsigned& r0, unsigned& r1, unsigned& r2,
                                        unsigned& r3, unsigned addr) {
    asm volatile("ldmatrix.sync.aligned.m8n8.x4.shared.b16 {%0,%1,%2,%3}, [%4];"
                 : "=r"(r0), "=r"(r1), "=r"(r2), "=r"(r3) : "r"(addr));
}
__device__ __forceinline__ void mma_bf16(float* d, unsigned a0, unsigned a1,
                                         unsigned a2, unsigned a3,
                                         unsigned b0, unsigned b1) {
    asm volatile(
        "mma.sync.aligned.m16n8k16.row.col.f32.bf16.bf16.f32 "
        "{%0,%1,%2,%3}, {%4,%5,%6,%7}, {%8,%9}, {%0,%1,%2,%3};"
        : "+f"(d[0]), "+f"(d[1]), "+f"(d[2]), "+f"(d[3])
        : "r"(a0), "r"(a1), "r"(a2), "r"(a3), "r"(b0), "r"(b1));
}

// ---------------------------------------------------------------------------
// mma.sync GEMM:  C[8192, N] = A'[8192,3840]bf16 @ Bt[N,3840]^T + bias
// CTA 128x128, 8 warps (2m x 4n), warp tile 64x32, BK=32, double buffer.
// MODE 1: A=g_a1, B=g_w1t, QKV scatter epilogue (N=3840).
// MODE 2: A=g_a2, B=g_w2t, plain C + bias (N=1280).
// ---------------------------------------------------------------------------
#define BK 32
#define APAD 40                       // 32 cols + 8 pad (80B rows, 16B aligned)
#define NUM_CHUNK 120                 // 3840 / 32

__device__ __forceinline__ void g_load_stage(
    const __nv_bfloat16* __restrict__ Ag, const __nv_bfloat16* __restrict__ Bg,
    unsigned aS, unsigned bS, int buf, int tid)
{
    unsigned abase = aS + (unsigned)buf * (128 * APAD * 2);
    unsigned bbase = bS + (unsigned)buf * (128 * APAD * 2);
#pragma unroll
    for (int it = 0; it < 4; it++) {
        int idx = tid + it * 256;         // 0..1023
        if (idx < 512) {
            int r = idx >> 2, s = idx & 3;
            CP_ASYNC16(abase + r * (APAD * 2) + s * 16, Ag + (size_t)r * KP + s * 8);
        } else {
            int j = idx - 512;
            int r = j >> 2, s = j & 3;
            CP_ASYNC16(bbase + r * (APAD * 2) + s * 16, Bg + (size_t)r * KP + s * 8);
        }
    }
    CP_COMMIT();
}

template<int MODE>
__global__ __launch_bounds__(256) void mma_gemm(
    const float* __restrict__ bias, float* __restrict__ C)
{
    __shared__ __align__(16) __nv_bfloat16 sA[2][128][APAD];
    __shared__ __align__(16) __nv_bfloat16 sB[2][128][APAD];

    const __nv_bfloat16* __restrict__ A  = (MODE == 1) ? g_a1 : g_a2;
    const __nv_bfloat16* __restrict__ Bt = (MODE == 1) ? g_w1t : g_w2t;

    const int tid = threadIdx.x;
    const int warp = tid >> 5;
    const int lane = tid & 31;
    const int wm = warp >> 2;          // 0..1
    const int wn = warp & 3;           // 0..3
    const int m0 = blockIdx.y * 128;
    const int n0 = blockIdx.x * 128;

    const unsigned aS = smem_u32(&sA[0][0][0]);
    const unsigned bS = smem_u32(&sB[0][0][0]);
    const __nv_bfloat16* Agb = A + (size_t)m0 * KP;
    const __nv_bfloat16* Bgb = Bt + (size_t)n0 * KP;

    float acc[4][4][4];
#pragma unroll
    for (int i = 0; i < 4; i++)
#pragma unroll
        for (int j = 0; j < 4; j++)
#pragma unroll
            for (int r = 0; r < 4; r++) acc[i][j][r] = 0.f;

    // ldmatrix source addresses (per warp, per k-step; buffer offset added later)
    // A x4: lanes 0-15 -> rows 0-15 @ kcol, lanes 16-31 -> rows 0-15 @ kcol+8
    const int a_row = wm * 64 + (lane & 15);
    const int a_kof = (lane >> 4) * 8;
    // B x4: group g=lane>>3: row = jj*16 + (g>>1)*8 + (lane&7), col = (g&1)*8
    const int b_row = wn * 32 + ((lane >> 4) & 1) * 8 + (lane & 7);
    const int b_kof = ((lane >> 3) & 1) * 8;

    g_load_stage(Agb, Bgb, aS, bS, 0, tid);

    for (int s = 0; s < NUM_CHUNK; s++) {
        if (s + 1 < NUM_CHUNK)
            g_load_stage(Agb + (s + 1) * BK, Bgb + (s + 1) * BK, aS, bS, (s + 1) & 1, tid);
        if (s + 1 < NUM_CHUNK) { CP_WAIT1(); } else { CP_WAIT0(); }
        __syncthreads();

        unsigned abuf = aS + (unsigned)(s & 1) * (128 * APAD * 2);
        unsigned bbuf = bS + (unsigned)(s & 1) * (128 * APAD * 2);
#pragma unroll
        for (int ks = 0; ks < 2; ks++) {
            unsigned afr[4][4];
            unsigned bfr[4][2];
#pragma unroll
            for (int i = 0; i < 4; i++) {
                unsigned addr = abuf + (a_row + i * 16) * (APAD * 2)
                              + (ks * 16 + a_kof) * 2;
                ldsm_x4(afr[i][0], afr[i][1], afr[i][2], afr[i][3], addr);
            }
#pragma unroll
            for (int jj = 0; jj < 2; jj++) {
                unsigned addr = bbuf + (b_row + jj * 16) * (APAD * 2)
                              + (ks * 16 + b_kof) * 2;
                ldsm_x4(bfr[2 * jj][0], bfr[2 * jj][1],
                        bfr[2 * jj + 1][0], bfr[2 * jj + 1][1], addr);
            }
#pragma unroll
            for (int i = 0; i < 4; i++)
#pragma unroll
                for (int j = 0; j < 4; j++)
                    mma_bf16(acc[i][j], afr[i][0], afr[i][1], afr[i][2], afr[i][3],
                             bfr[j][0], bfr[j][1]);
        }
        __syncthreads();
    }

    // Epilogue
#pragma unroll
    for (int i = 0; i < 4; i++) {
#pragma unroll
        for (int j = 0; j < 4; j++) {
#pragma unroll
            for (int half = 0; half < 2; half++) {
                int m = m0 + wm * 64 + i * 16 + (lane >> 2) + half * 8;
                int n = n0 + wn * 32 + j * 8 + (lane & 3) * 2;
                float v0 = acc[i][j][2 * half]     + bias[n];
                float v1 = acc[i][j][2 * half + 1] + bias[n + 1];
                if (MODE == 2) {
                    float2 o = make_float2(v0, v1);
                    *(float2*)(C + (size_t)m * 1280 + n) = o;
                } else {
                    int which = n / DD;
                    int rem = n - which * DD;
                    int h = rem / HD;
                    int dd = rem - h * HD;
                    float* dst = (which == 0) ? g_q : (which == 1) ? g_k : g_v;
                    int b = m >> 10, l = m & 1023;
                    float2 o = make_float2(v0, v1);
                    *(float2*)(dst + ((size_t)((b * HH + h) * LL + l)) * HD + dd) = o;
                }
            }
        }
    }
}

// ---------------------------------------------------------------------------
// Split fp32 [M,1280] -> bf16 [M,3840] as [hi | lo | hi]
// WHICH 1: src = input hidden (param), dst = g_a1.  WHICH 2: src=g_o, dst=g_a2.
// ---------------------------------------------------------------------------
template<int WHICH>
__global__ void split_kernel(const float* __restrict__ Xin, int total)
{
    const float* __restrict__ X = (WHICH == 1) ? Xin : g_o;
    __nv_bfloat16* __restrict__ Y = (WHICH == 1) ? g_a1 : g_a2;
    int i = blockIdx.x * blockDim.x + threadIdx.x;
    if (i >= total) return;
    int m = i / 1280, k = i - m * 1280;
    float x = X[i];
    __nv_bfloat16 h = __float2bfloat16(x);
    __nv_bfloat16 l = __float2bfloat16(x - __bfloat162float(h));
    size_t ro = (size_t)m * KP;
    Y[ro + k] = h;
    Y[ro + 1280 + k] = l;
    Y[ro + 2560 + k] = h;
}

// ---------------------------------------------------------------------------
// Transpose+split W [Kdim, Ncols] fp32 -> Yt [Ncols, 3840] bf16:
// Yt[n][k]=hi, Yt[n][1280+k]=hi, Yt[n][2560+k]=lo  (pairs with A' = hi|lo|hi)
// ---------------------------------------------------------------------------
template<int WHICH>
__global__ void wsplit_kernel(const float* __restrict__ W, int Ncols)
{
    __nv_bfloat16* __restrict__ Yt = (WHICH == 1) ? g_w1t : g_w2t;
    __shared__ float t[32][33];
    int k0 = blockIdx.y * 32, n0 = blockIdx.x * 32;
    int tx = threadIdx.x, ty = threadIdx.y;    // 32 x 8
#pragma unroll
    for (int r = 0; r < 4; r++)
        t[ty + 8 * r][tx] = W[(size_t)(k0 + ty + 8 * r) * Ncols + n0 + tx];
    __syncthreads();
#pragma unroll
    for (int r = 0; r < 4; r++) {
        int kk = tx, nn = ty + 8 * r;
        float x = t[kk][nn];
        __nv_bfloat16 h = __float2bfloat16(x);
        __nv_bfloat16 l = __float2bfloat16(x - __bfloat162float(h));
        size_t ro = (size_t)(n0 + nn) * KP + k0 + kk;
        Yt[ro] = h;
        Yt[ro + 1280] = h;
        Yt[ro + 2560] = l;
    }
}

// ---------------------------------------------------------------------------
// RoPE on g_q, g_k in place.
// ---------------------------------------------------------------------------
__global__ void rope_kernel(const float* __restrict__ rot)
{
    const int total = BB * HH * LL * (HD / 2);
    int idx = blockIdx.x * blockDim.x + threadIdx.x;
    if (idx >= total) return;
    int j = idx % 40;
    int l = (idx / 40) & 1023;
    int bh = idx / (40 * 1024);
    float r = rot[l * 40 + j];
    float s, c;
    sincosf(r, &s, &c);
    size_t base = ((size_t)bh * LL + l) * HD;

    float q1 = g_q[base + j], q2 = g_q[base + j + 40];
    g_q[base + j]      = q1 * c - q2 * s;
    g_q[base + j + 40] = q2 * c + q1 * s;

    float k1 = g_k[base + j], k2 = g_k[base + j + 40];
    g_k[base + j]      = k1 * c - k2 * s;
    g_k[base + j + 40] = k2 * c + k1 * s;
}

// ---------------------------------------------------------------------------
// Causal flash attention, fp32 (R1-verified).
// ---------------------------------------------------------------------------
__global__ __launch_bounds__(128) void attn_kernel()
{
    __shared__ float Ks[32][80];
    __shared__ float Vs[32][80];

    const int bh = blockIdx.y;
    const int row = blockIdx.x * 128 + threadIdx.x;
    const float scale = 0.1118033988749895f;

    const float* qp = g_q + ((size_t)bh * LL + row) * HD;
    float q[80];
#pragma unroll
    for (int d4 = 0; d4 < 20; d4++) {
        float4 t = ((const float4*)qp)[d4];
        q[4*d4+0] = t.x * scale; q[4*d4+1] = t.y * scale;
        q[4*d4+2] = t.z * scale; q[4*d4+3] = t.w * scale;
    }

    float acc[80];
#pragma unroll
    for (int d = 0; d < 80; d++) acc[d] = 0.f;
    float mrun = -3.0e38f, lsum = 0.f;

    const int ntiles = (blockIdx.x + 1) * 4;
    const float4* kbase = (const float4*)(g_k + (size_t)bh * LL * HD);
    const float4* vbase = (const float4*)(g_v + (size_t)bh * LL * HD);

    for (int t = 0; t < ntiles; t++) {
        __syncthreads();
#pragma unroll
        for (int i = 0; i < 5; i++) {
            int idx = threadIdx.x + i * 128;
            ((float4*)Ks)[idx] = kbase[t * 640 + idx];
            ((float4*)Vs)[idx] = vbase[t * 640 + idx];
        }
        __syncthreads();
        int kg0 = t * 32;
#pragma unroll 1
        for (int g = 0; g < 2; g++) {
            float s[16];
#pragma unroll
            for (int j = 0; j < 16; j++) {
                int jj = g * 16 + j;
                const float4* krow = (const float4*)Ks[jj];
                float sum = 0.f;
#pragma unroll
                for (int d4 = 0; d4 < 20; d4++) {
                    float4 kv = krow[d4];
                    sum = fmaf(q[4*d4+0], kv.x, sum);
                    sum = fmaf(q[4*d4+1], kv.y, sum);
                    sum = fmaf(q[4*d4+2], kv.z, sum);
                    sum = fmaf(q[4*d4+3], kv.w, sum);
                }
                s[j] = (kg0 + jj <= row) ? sum : -3.0e38f;
            }
            float mn = mrun;
#pragma unroll
            for (int j = 0; j < 16; j++) mn = fmaxf(mn, s[j]);
            float corr = __expf(mrun - mn);
            mrun = mn;
            lsum *= corr;
#pragma unroll
            for (int d = 0; d < 80; d++) acc[d] *= corr;
#pragma unroll
            for (int j = 0; j < 16; j++) {
                float p = __expf(s[j] - mn);
                lsum += p;
                const float4* vrow = (const float4*)Vs[g * 16 + j];
#pragma unroll
                for (int d4 = 0; d4 < 20; d4++) {
                    float4 vv = vrow[d4];
                    acc[4*d4+0] = fmaf(p, vv.x, acc[4*d4+0]);
                    acc[4*d4+1] = fmaf(p, vv.y, acc[4*d4+1]);
                    acc[4*d4+2] = fmaf(p, vv.z, acc[4*d4+2]);
                    acc[4*d4+3] = fmaf(p, vv.w, acc[4*d4+3]);
                }
            }
        }
    }

    float inv = 1.f / lsum;
    const int b = bh >> 4, h = bh & 15;
    float* op = g_o + ((size_t)(b * LL + row)) * DD + h * HD;
#pragma unroll
    for (int d4 = 0; d4 < 20; d4++) {
        float4 o;
        o.x = acc[4*d4+0] * inv; o.y = acc[4*d4+1] * inv;
        o.z = acc[4*d4+2] * inv; o.w = acc[4*d4+3] * inv;
        *(float4*)(op + 4 * d4) = o;
    }
}

// ---------------------------------------------------------------------------
extern "C" void kernel_launch(void* const* d_in, const int* in_sizes, int n_in,
                              void* d_out, int out_size)
{
    const float* hidden = (const float*)d_in[0];   // (8,1024,1280)
    const float* rot    = (const float*)d_in[1];   // (1024,40)
    const float* Wqkv   = (const float*)d_in[2];   // (1280,3840)
    const float* bqkv   = (const float*)d_in[3];   // (3840,)
    const float* Wproj  = (const float*)d_in[4];   // (1280,1280)
    const float* bproj  = (const float*)d_in[5];   // (1280,)
    float* out = (float*)d_out;                    // (8,1024,1280)

    // 0) precision-split conversions
    {
        int total = MTOT * 1280;
        split_kernel<1><<<(total + 255) / 256, 256>>>(hidden, total);
        dim3 blk(32, 8);
        wsplit_kernel<1><<<dim3(3840 / 32, 1280 / 32), blk>>>(Wqkv, 3840);
        wsplit_kernel<2><<<dim3(1280 / 32, 1280 / 32), blk>>>(Wproj, 1280);
    }

    // 1) QKV GEMM (mma.sync bf16) with scatter + bias
    mma_gemm<1><<<dim3(3840 / 128, MTOT / 128), 256>>>(bqkv, nullptr);

    // 2) RoPE
    {
        const int total = BB * HH * LL * (HD / 2);
        rope_kernel<<<(total + 255) / 256, 256>>>(rot);
    }

    // 3) Causal attention
    attn_kernel<<<dim3(LL / 128, BB * HH), 128>>>();

    // 4) split attention output, then output projection (mma.sync bf16)
    {
        int total = MTOT * 1280;
        split_kernel<2><<<(total + 255) / 256, 256>>>(nullptr, total);
    }
    mma_gemm<2><<<dim3(1280 / 128, MTOT / 128), 256>>>(bproj, out);
}

// round 13
// speedup vs baseline: 1.9583x; 1.0856x over previous
#include <cuda_runtime.h>
#include <cuda_bf16.h>
#include <cstdint>
#include <stdint.h>
#include <math.h>

// Problem constants
#define BB 8
#define LL 1024
#define DD 1280
#define HH 16
#define HD 80
#define MTOT (BB*LL)      // 8192
#define KP   3840         // stacked K' = 3*1280

// Scratch (__device__ globals; allocation-free rule)
__device__ float g_q[(size_t)BB*HH*LL*HD];   // [B,H,L,hd]
__device__ float g_k[(size_t)BB*HH*LL*HD];
__device__ float g_v[(size_t)BB*HH*LL*HD];
__device__ float g_o[(size_t)BB*LL*DD];      // attention output, [B,L,D]
__device__ __nv_bfloat16 g_a1[(size_t)MTOT*KP];   // [8192][3840] hi|lo|hi of hidden
__device__ __nv_bfloat16 g_a2[(size_t)MTOT*KP];   // [8192][3840] hi|lo|hi of attn out
__device__ __nv_bfloat16 g_w1t[(size_t)3840*KP];  // Wqkv^T stacked: [n][k']
__device__ __nv_bfloat16 g_w2t[(size_t)1280*KP];  // Wproj^T stacked: [n][k']

// ---------------------------------------------------------------------------
// PTX helpers (compute_103-safe: cp.async + ldmatrix + mma.sync only)
// ---------------------------------------------------------------------------
__device__ __forceinline__ unsigned smem_u32(const void* p) {
    unsigned a;
    asm("{ .reg .u64 t; cvta.to.shared.u64 t, %1; cvt.u32.u64 %0, t; }" : "=r"(a) : "l"(p));
    return a;
}
#define CP_ASYNC16(dst, src) \
    asm volatile("cp.async.cg.shared.global [%0], [%1], 16;" :: "r"(dst), "l"(src) : "memory")
#define CP_COMMIT() asm volatile("cp.async.commit_group;" ::: "memory")
#define CP_WAIT1()  asm volatile("cp.async.wait_group 1;" ::: "memory")
#define CP_WAIT0()  asm volatile("cp.async.wait_group 0;" ::: "memory")

__device__ __forceinline__ void ldsm_x4(unsigned& r0, unsigned& r1, unsigned& r2,
                                        unsigned& r3, unsigned addr) {
    asm volatile("ldmatrix.sync.aligned.m8n8.x4.shared.b16 {%0,%1,%2,%3}, [%4];"
                 : "=r"(r0), "=r"(r1), "=r"(r2), "=r"(r3) : "r"(addr));
}
__device__ __forceinline__ void mma_bf16(float* d, unsigned a0, unsigned a1,
                                         unsigned a2, unsigned a3,
                                         unsigned b0, unsigned b1) {
    asm volatile(
        "mma.sync.aligned.m16n8k16.row.col.f32.bf16.bf16.f32 "
        "{%0,%1,%2,%3}, {%4,%5,%6,%7}, {%8,%9}, {%0,%1,%2,%3};"
        : "+f"(d[0]), "+f"(d[1]), "+f"(d[2]), "+f"(d[3])
        : "r"(a0), "r"(a1), "r"(a2), "r"(a3), "r"(b0), "r"(b1));
}

// ---------------------------------------------------------------------------
// mma.sync GEMM:  C[8192, N] = A'[8192,3840]bf16 @ Bt[N,3840]^T + bias
// CTA 128x128, 8 warps (2m x 4n), warp tile 64x32, BK=64, double buffer
// (dynamic smem, 72KB). MODE 1: QKV scatter epilogue. MODE 2: plain C+bias.
// ---------------------------------------------------------------------------
#define BK 64
#define ROWB 144                      // bytes per smem row: 64 bf16 + 8 pad
#define STB (128*ROWB)                // 18432 bytes per operand per buffer
#define GEMM_SMEM (4*STB)             // A0,A1,B0,B1 = 73728
#define NUM_CHUNK 60                  // 3840 / 64

__device__ __forceinline__ void g_load_stage(
    const __nv_bfloat16* __restrict__ Ag, const __nv_bfloat16* __restrict__ Bg,
    unsigned aS, unsigned bS, int buf, int tid)
{
    unsigned abase = aS + (unsigned)buf * STB;
    unsigned bbase = bS + (unsigned)buf * STB;
#pragma unroll
    for (int it = 0; it < 8; it++) {
        int idx = tid + it * 256;         // 0..2047
        if (idx < 1024) {
            int r = idx >> 3, s = idx & 7;
            CP_ASYNC16(abase + r * ROWB + s * 16, Ag + (size_t)r * KP + s * 8);
        } else {
            int j = idx - 1024;
            int r = j >> 3, s = j & 7;
            CP_ASYNC16(bbase + r * ROWB + s * 16, Bg + (size_t)r * KP + s * 8);
        }
    }
    CP_COMMIT();
}

template<int MODE>
__global__ __launch_bounds__(256) void mma_gemm(
    const float* __restrict__ bias, float* __restrict__ C)
{
    extern __shared__ __align__(16) char gsm[];

    const __nv_bfloat16* __restrict__ A  = (MODE == 1) ? g_a1 : g_a2;
    const __nv_bfloat16* __restrict__ Bt = (MODE == 1) ? g_w1t : g_w2t;

    const int tid = threadIdx.x;
    const int warp = tid >> 5;
    const int lane = tid & 31;
    const int wm = warp >> 2;          // 0..1
    const int wn = warp & 3;           // 0..3
    const int m0 = blockIdx.y * 128;
    const int n0 = blockIdx.x * 128;

    const unsigned aS = smem_u32(gsm);
    const unsigned bS = aS + 2 * STB;
    const __nv_bfloat16* Agb = A + (size_t)m0 * KP;
    const __nv_bfloat16* Bgb = Bt + (size_t)n0 * KP;

    float acc[4][4][4];
#pragma unroll
    for (int i = 0; i < 4; i++)
#pragma unroll
        for (int j = 0; j < 4; j++)
#pragma unroll
            for (int r = 0; r < 4; r++) acc[i][j][r] = 0.f;

    // ldmatrix lane->addr mapping (validated in R8)
    const int a_row = wm * 64 + (lane & 15);
    const int a_kof = (lane >> 4) * 8;
    const int b_row = wn * 32 + ((lane >> 4) & 1) * 8 + (lane & 7);
    const int b_kof = ((lane >> 3) & 1) * 8;

    g_load_stage(Agb, Bgb, aS, bS, 0, tid);

    for (int s = 0; s < NUM_CHUNK; s++) {
        if (s + 1 < NUM_CHUNK)
            g_load_stage(Agb + (s + 1) * BK, Bgb + (s + 1) * BK, aS, bS, (s + 1) & 1, tid);
        if (s + 1 < NUM_CHUNK) { CP_WAIT1(); } else { CP_WAIT0(); }
        __syncthreads();

        unsigned abuf = aS + (unsigned)(s & 1) * STB;
        unsigned bbuf = bS + (unsigned)(s & 1) * STB;
#pragma unroll
        for (int ks = 0; ks < 4; ks++) {
            unsigned afr[4][4];
            unsigned bfr[4][2];
#pragma unroll
            for (int i = 0; i < 4; i++) {
                unsigned addr = abuf + (a_row + i * 16) * ROWB
                              + (ks * 16 + a_kof) * 2;
                ldsm_x4(afr[i][0], afr[i][1], afr[i][2], afr[i][3], addr);
            }
#pragma unroll
            for (int jj = 0; jj < 2; jj++) {
                unsigned addr = bbuf + (b_row + jj * 16) * ROWB
                              + (ks * 16 + b_kof) * 2;
                ldsm_x4(bfr[2 * jj][0], bfr[2 * jj][1],
                        bfr[2 * jj + 1][0], bfr[2 * jj + 1][1], addr);
            }
#pragma unroll
            for (int i = 0; i < 4; i++)
#pragma unroll
                for (int j = 0; j < 4; j++)
                    mma_bf16(acc[i][j], afr[i][0], afr[i][1], afr[i][2], afr[i][3],
                             bfr[j][0], bfr[j][1]);
        }
        __syncthreads();
    }

    // Epilogue (unchanged from R8)
#pragma unroll
    for (int i = 0; i < 4; i++) {
#pragma unroll
        for (int j = 0; j < 4; j++) {
#pragma unroll
            for (int half = 0; half < 2; half++) {
                int m = m0 + wm * 64 + i * 16 + (lane >> 2) + half * 8;
                int n = n0 + wn * 32 + j * 8 + (lane & 3) * 2;
                float v0 = acc[i][j][2 * half]     + bias[n];
                float v1 = acc[i][j][2 * half + 1] + bias[n + 1];
                if (MODE == 2) {
                    float2 o = make_float2(v0, v1);
                    *(float2*)(C + (size_t)m * 1280 + n) = o;
                } else {
                    int which = n / DD;
                    int rem = n - which * DD;
                    int h = rem / HD;
                    int dd = rem - h * HD;
                    float* dst = (which == 0) ? g_q : (which == 1) ? g_k : g_v;
                    int b = m >> 10, l = m & 1023;
                    float2 o = make_float2(v0, v1);
                    *(float2*)(dst + ((size_t)((b * HH + h) * LL + l)) * HD + dd) = o;
                }
            }
        }
    }
}

// ---------------------------------------------------------------------------
// Split fp32 [M,1280] -> bf16 [M,3840] as [hi | lo | hi]
// ---------------------------------------------------------------------------
template<int WHICH>
__global__ void split_kernel(const float* __restrict__ Xin, int total)
{
    const float* __restrict__ X = (WHICH == 1) ? Xin : g_o;
    __nv_bfloat16* __restrict__ Y = (WHICH == 1) ? g_a1 : g_a2;
    int i = blockIdx.x * blockDim.x + threadIdx.x;
    if (i >= total) return;
    int m = i / 1280, k = i - m * 1280;
    float x = X[i];
    __nv_bfloat16 h = __float2bfloat16(x);
    __nv_bfloat16 l = __float2bfloat16(x - __bfloat162float(h));
    size_t ro = (size_t)m * KP;
    Y[ro + k] = h;
    Y[ro + 1280 + k] = l;
    Y[ro + 2560 + k] = h;
}

// ---------------------------------------------------------------------------
// Transpose+split W [Kdim, Ncols] fp32 -> Yt [Ncols, 3840] bf16
// ---------------------------------------------------------------------------
template<int WHICH>
__global__ void wsplit_kernel(const float* __restrict__ W, int Ncols)
{
    __nv_bfloat16* __restrict__ Yt = (WHICH == 1) ? g_w1t : g_w2t;
    __shared__ float t[32][33];
    int k0 = blockIdx.y * 32, n0 = blockIdx.x * 32;
    int tx = threadIdx.x, ty = threadIdx.y;    // 32 x 8
#pragma unroll
    for (int r = 0; r < 4; r++)
        t[ty + 8 * r][tx] = W[(size_t)(k0 + ty + 8 * r) * Ncols + n0 + tx];
    __syncthreads();
#pragma unroll
    for (int r = 0; r < 4; r++) {
        int kk = tx, nn = ty + 8 * r;
        float x = t[kk][nn];
        __nv_bfloat16 h = __float2bfloat16(x);
        __nv_bfloat16 l = __float2bfloat16(x - __bfloat162float(h));
        size_t ro = (size_t)(n0 + nn) * KP + k0 + kk;
        Yt[ro] = h;
        Yt[ro + 1280] = h;
        Yt[ro + 2560] = l;
    }
}

// ---------------------------------------------------------------------------
// RoPE on g_q, g_k in place.
// ---------------------------------------------------------------------------
__global__ void rope_kernel(const float* __restrict__ rot)
{
    const int total = BB * HH * LL * (HD / 2);
    int idx = blockIdx.x * blockDim.x + threadIdx.x;
    if (idx >= total) return;
    int j = idx % 40;
    int l = (idx / 40) & 1023;
    int bh = idx / (40 * 1024);
    float r = rot[l * 40 + j];
    float s, c;
    sincosf(r, &s, &c);
    size_t base = ((size_t)bh * LL + l) * HD;

    float q1 = g_q[base + j], q2 = g_q[base + j + 40];
    g_q[base + j]      = q1 * c - q2 * s;
    g_q[base + j + 40] = q2 * c + q1 * s;

    float k1 = g_k[base + j], k2 = g_k[base + j + 40];
    g_k[base + j]      = k1 * c - k2 * s;
    g_k[base + j + 40] = k2 * c + k1 * s;
}

// ---------------------------------------------------------------------------
// Causal flash attention, fp32 (R1-verified).
// ---------------------------------------------------------------------------
__global__ __launch_bounds__(128) void attn_kernel()
{
    __shared__ float Ks[32][80];
    __shared__ float Vs[32][80];

    const int bh = blockIdx.y;
    const int row = blockIdx.x * 128 + threadIdx.x;
    const float scale = 0.1118033988749895f;

    const float* qp = g_q + ((size_t)bh * LL + row) * HD;
    float q[80];
#pragma unroll
    for (int d4 = 0; d4 < 20; d4++) {
        float4 t = ((const float4*)qp)[d4];
        q[4*d4+0] = t.x * scale; q[4*d4+1] = t.y * scale;
        q[4*d4+2] = t.z * scale; q[4*d4+3] = t.w * scale;
    }

    float acc[80];
#pragma unroll
    for (int d = 0; d < 80; d++) acc[d] = 0.f;
    float mrun = -3.0e38f, lsum = 0.f;

    const int ntiles = (blockIdx.x + 1) * 4;
    const float4* kbase = (const float4*)(g_k + (size_t)bh * LL * HD);
    const float4* vbase = (const float4*)(g_v + (size_t)bh * LL * HD);

    for (int t = 0; t < ntiles; t++) {
        __syncthreads();
#pragma unroll
        for (int i = 0; i < 5; i++) {
            int idx = threadIdx.x + i * 128;
            ((float4*)Ks)[idx] = kbase[t * 640 + idx];
            ((float4*)Vs)[idx] = vbase[t * 640 + idx];
        }
        __syncthreads();
        int kg0 = t * 32;
#pragma unroll 1
        for (int g = 0; g < 2; g++) {
            float s[16];
#pragma unroll
            for (int j = 0; j < 16; j++) {
                int jj = g * 16 + j;
                const float4* krow = (const float4*)Ks[jj];
                float sum = 0.f;
#pragma unroll
                for (int d4 = 0; d4 < 20; d4++) {
                    float4 kv = krow[d4];
                    sum = fmaf(q[4*d4+0], kv.x, sum);
                    sum = fmaf(q[4*d4+1], kv.y, sum);
                    sum = fmaf(q[4*d4+2], kv.z, sum);
                    sum = fmaf(q[4*d4+3], kv.w, sum);
                }
                s[j] = (kg0 + jj <= row) ? sum : -3.0e38f;
            }
            float mn = mrun;
#pragma unroll
            for (int j = 0; j < 16; j++) mn = fmaxf(mn, s[j]);
            float corr = __expf(mrun - mn);
            mrun = mn;
            lsum *= corr;
#pragma unroll
            for (int d = 0; d < 80; d++) acc[d] *= corr;
#pragma unroll
            for (int j = 0; j < 16; j++) {
                float p = __expf(s[j] - mn);
                lsum += p;
                const float4* vrow = (const float4*)Vs[g * 16 + j];
#pragma unroll
                for (int d4 = 0; d4 < 20; d4++) {
                    float4 vv = vrow[d4];
                    acc[4*d4+0] = fmaf(p, vv.x, acc[4*d4+0]);
                    acc[4*d4+1] = fmaf(p, vv.y, acc[4*d4+1]);
                    acc[4*d4+2] = fmaf(p, vv.z, acc[4*d4+2]);
                    acc[4*d4+3] = fmaf(p, vv.w, acc[4*d4+3]);
                }
            }
        }
    }

    float inv = 1.f / lsum;
    const int b = bh >> 4, h = bh & 15;
    float* op = g_o + ((size_t)(b * LL + row)) * DD + h * HD;
#pragma unroll
    for (int d4 = 0; d4 < 20; d4++) {
        float4 o;
        o.x = acc[4*d4+0] * inv; o.y = acc[4*d4+1] * inv;
        o.z = acc[4*d4+2] * inv; o.w = acc[4*d4+3] * inv;
        *(float4*)(op + 4 * d4) = o;
    }
}

// ---------------------------------------------------------------------------
extern "C" void kernel_launch(void* const* d_in, const int* in_sizes, int n_in,
                              void* d_out, int out_size)
{
    const float* hidden = (const float*)d_in[0];   // (8,1024,1280)
    const float* rot    = (const float*)d_in[1];   // (1024,40)
    const float* Wqkv   = (const float*)d_in[2];   // (1280,3840)
    const float* bqkv   = (const float*)d_in[3];   // (3840,)
    const float* Wproj  = (const float*)d_in[4];   // (1280,1280)
    const float* bproj  = (const float*)d_in[5];   // (1280,)
    float* out = (float*)d_out;                    // (8,1024,1280)

    cudaFuncSetAttribute(mma_gemm<1>, cudaFuncAttributeMaxDynamicSharedMemorySize, GEMM_SMEM);
    cudaFuncSetAttribute(mma_gemm<2>, cudaFuncAttributeMaxDynamicSharedMemorySize, GEMM_SMEM);

    // 0) precision-split conversions
    {
        int total = MTOT * 1280;
        split_kernel<1><<<(total + 255) / 256, 256>>>(hidden, total);
        dim3 blk(32, 8);
        wsplit_kernel<1><<<dim3(3840 / 32, 1280 / 32), blk>>>(Wqkv, 3840);
        wsplit_kernel<2><<<dim3(1280 / 32, 1280 / 32), blk>>>(Wproj, 1280);
    }

    // 1) QKV GEMM (mma.sync bf16, BK=64) with scatter + bias
    mma_gemm<1><<<dim3(3840 / 128, MTOT / 128), 256, GEMM_SMEM>>>(bqkv, nullptr);

    // 2) RoPE
    {
        const int total = BB * HH * LL * (HD / 2);
        rope_kernel<<<(total + 255) / 256, 256>>>(rot);
    }

    // 3) Causal attention (fp32, proven)
    attn_kernel<<<dim3(LL / 128, BB * HH), 128>>>();

    // 4) split attention output, then output projection
    {
        int total = MTOT * 1280;
        split_kernel<2><<<(total + 255) / 256, 256>>>(nullptr, total);
    }
    mma_gemm<2><<<dim3(1280 / 128, MTOT / 128), 256, GEMM_SMEM>>>(bproj, out);
}